// round 15
// baseline (speedup 1.0000x reference)
#include <cuda_runtime.h>
#include <math.h>

#define BB 2
#define QQ 2048
#define FF 1538
#define CH 514          // faces per smem chunk (3 chunks cover 1538)

__device__ float g_res[BB * QQ];
__device__ float g_partial[BB];
__device__ unsigned int g_done = 0;

// ---------------------------------------------------------------------------
// fast helpers
// ---------------------------------------------------------------------------
__device__ __forceinline__ float sqrt_approx(float x) {
    float r; asm("sqrt.approx.f32 %0, %1;" : "=f"(r) : "f"(x)); return r;
}
__device__ __forceinline__ float rcp_approx(float x) {
    float r; asm("rcp.approx.f32 %0, %1;" : "=f"(r) : "f"(x)); return r;
}

// atan2 via quadrant folding + degree-11 odd minimax poly (|err| ~ 3e-6)
__device__ __forceinline__ float fast_atan2(float y, float x) {
    float ax = fabsf(x), ay = fabsf(y);
    float mx = fmaxf(ax, ay), mn = fminf(ax, ay);
    float t = mn * rcp_approx(mx);
    float s = t * t;
    float p =             -0.01172120f;
    p = fmaf(p, s,  0.05265332f);
    p = fmaf(p, s, -0.11643287f);
    p = fmaf(p, s,  0.19354346f);
    p = fmaf(p, s, -0.33262347f);
    p = fmaf(p, s,  0.99997726f);
    float r = p * t;
    if (ay > ax) r = 1.57079632679f - r;
    if (x < 0.0f) r = 3.14159265359f - r;
    return copysignf(r, y);
}

// ---------------------------------------------------------------------------
// Kernel 1: winding numbers + residuals.
// Record: [0..2]=A [3..5]=B [6..8]=C [9..11]=N=(B-A)x(C-A)  (N built in staging)
// num = A.N - p.N  (identity: (A-p).((B-p)x(C-p)) = A.(BxC) - p.N, A.(BxC)=A.N)
// TWO queries per warp (ILP=2), TWO warps per query pair (face split).
// 128-thread blocks, 4 queries/block -> 1024 blocks.
// ---------------------------------------------------------------------------
__global__ __launch_bounds__(128) void wn_kernel(const float* __restrict__ points,
                                                 const float* __restrict__ tris,
                                                 const float* __restrict__ occ) {
    __shared__ float st[CH * 12];
    __shared__ float sacc[8];     // [warp*2 + whichQuery]

    int tid  = threadIdx.x;
    int warp = tid >> 5;          // 0..3
    int lane = tid & 31;
    int pair = warp >> 1;         // query pair 0/1 within block
    int half = warp & 1;          // face-stride half

    int qA = blockIdx.x * 4 + pair * 2;   // 1024 blocks * 4 queries = 4096
    int qB = qA + 1;
    int b  = qA >> 11;                    // batch (uniform per block)

    float pxA = points[qA * 3 + 0], pyA = points[qA * 3 + 1], pzA = points[qA * 3 + 2];
    float pxB = points[qB * 3 + 0], pyB = points[qB * 3 + 1], pzB = points[qB * 3 + 2];

    const float* tb = tris + (size_t)b * FF * 9;

    float accA = 0.0f, accB = 0.0f;
    for (int base = 0; base < FF; base += CH) {
        int nf = min(CH, FF - base);
        __syncthreads();
        // stage: copy face + compute its normal N into spare slots
        for (int f = tid; f < nf; f += 128) {
            const float* src = tb + (size_t)(base + f) * 9;
            float Ax = src[0], Ay = src[1], Az = src[2];
            float Bx = src[3], By = src[4], Bz = src[5];
            float Cx = src[6], Cy = src[7], Cz = src[8];
            float e1x = Bx - Ax, e1y = By - Ay, e1z = Bz - Az;
            float e2x = Cx - Ax, e2y = Cy - Ay, e2z = Cz - Az;
            float* dst = &st[f * 12];
            dst[0] = Ax; dst[1] = Ay; dst[2]  = Az;
            dst[3] = Bx; dst[4] = By; dst[5]  = Bz;
            dst[6] = Cx; dst[7] = Cy; dst[8]  = Cz;
            dst[9]  = e1y * e2z - e1z * e2y;
            dst[10] = e1z * e2x - e1x * e2z;
            dst[11] = e1x * e2y - e1y * e2x;
        }
        __syncthreads();

        for (int f = half * 32 + lane; f < nf; f += 64) {
            const float4* t4 = (const float4*)&st[f * 12];
            float4 v0 = t4[0];   // Ax Ay Az Bx
            float4 v1 = t4[1];   // By Bz Cx Cy
            float4 v2 = t4[2];   // Cz Nx Ny Nz

            // shared across both queries: det = A.N
            float det = fmaf(v0.x, v2.y, fmaf(v0.y, v2.z, v0.z * v2.w));

            // ----- query A -----
            {
                float ax = v0.x - pxA, ay = v0.y - pyA, az = v0.z - pzA;
                float bx = v0.w - pxA, by = v1.x - pyA, bz = v1.y - pzA;
                float cx = v1.z - pxA, cy = v1.w - pyA, cz = v2.x - pzA;

                float na = sqrt_approx(fmaf(ax, ax, fmaf(ay, ay, az * az)));
                float nb = sqrt_approx(fmaf(bx, bx, fmaf(by, by, bz * bz)));
                float nc = sqrt_approx(fmaf(cx, cx, fmaf(cy, cy, cz * cz)));

                float num = fmaf(-pxA, v2.y, fmaf(-pyA, v2.z, fmaf(-pzA, v2.w, det)));
                float d01 = fmaf(ax, bx, fmaf(ay, by, az * bz));
                float d12 = fmaf(bx, cx, fmaf(by, cy, bz * cz));
                float d02 = fmaf(ax, cx, fmaf(ay, cy, az * cz));

                float den = fmaf(na * nb, nc, fmaf(d01, nc, fmaf(d02, nb, d12 * na)));
                accA += fast_atan2(num, den);
            }
            // ----- query B -----
            {
                float ax = v0.x - pxB, ay = v0.y - pyB, az = v0.z - pzB;
                float bx = v0.w - pxB, by = v1.x - pyB, bz = v1.y - pzB;
                float cx = v1.z - pxB, cy = v1.w - pyB, cz = v2.x - pzB;

                float na = sqrt_approx(fmaf(ax, ax, fmaf(ay, ay, az * az)));
                float nb = sqrt_approx(fmaf(bx, bx, fmaf(by, by, bz * bz)));
                float nc = sqrt_approx(fmaf(cx, cx, fmaf(cy, cy, cz * cz)));

                float num = fmaf(-pxB, v2.y, fmaf(-pyB, v2.z, fmaf(-pzB, v2.w, det)));
                float d01 = fmaf(ax, bx, fmaf(ay, by, az * bz));
                float d12 = fmaf(bx, cx, fmaf(by, cy, bz * cz));
                float d02 = fmaf(ax, cx, fmaf(ay, cy, az * cz));

                float den = fmaf(na * nb, nc, fmaf(d01, nc, fmaf(d02, nb, d12 * na)));
                accB += fast_atan2(num, den);
            }
        }
    }

    #pragma unroll
    for (int o = 16; o > 0; o >>= 1) {
        accA += __shfl_xor_sync(0xFFFFFFFFu, accA, o);
        accB += __shfl_xor_sync(0xFFFFFFFFu, accB, o);
    }

    if (lane == 0) {
        sacc[warp * 2 + 0] = accA;
        sacc[warp * 2 + 1] = accB;
    }
    __syncthreads();

    if (tid < 4) {  // tid = local query index 0..3
        int p    = tid >> 1;
        int qloc = tid & 1;
        float tot = sacc[(p * 2 + 0) * 2 + qloc] + sacc[(p * 2 + 1) * 2 + qloc];
        int q = blockIdx.x * 4 + tid;
        float wn = tot * 0.15915494309189535f;   // (2*atan2 sum)/(4*pi)
        g_res[q] = wn - occ[q];
    }
}

// ---------------------------------------------------------------------------
// Kernel 2: robust weighting. 1024 threads/batch.
// Linear-binned exact k-select (1024 bins over [min,max]) with rank small-
// select; proven 8-bit radix-select kept as exact fallback for fat bins.
// ---------------------------------------------------------------------------
__device__ __forceinline__ unsigned int fkey(float f) {
    unsigned int u = __float_as_uint(f);
    return (u & 0x80000000u) ? ~u : (u | 0x80000000u);
}
__device__ __forceinline__ float key_to_float(unsigned int k) {
    unsigned int bits = (k & 0x80000000u) ? (k ^ 0x80000000u) : ~k;
    return __uint_as_float(bits);
}

struct SelShared {
    unsigned int hist[1024];
    unsigned int wtot[32];
    unsigned int bc[3];
    float        smn[32];
    float        smx[32];
    float        candf[128];
    unsigned int candu[64];
    unsigned int ccnt;
    float        result;
};

// ---- fallback: proven 8-bit radix select (uses hist[0..255], wtot[0..7]) ----
__device__ unsigned int radix_select(const unsigned int* keys, SelShared* ss,
                                     int tid, int k) {
    int wid  = tid >> 5;
    int lane = tid & 31;
    unsigned int prefix = 0;

    for (int shift = 24; shift >= 0; shift -= 8) {
        if (tid < 256) ss->hist[tid] = 0;
        if (tid == 0)  ss->ccnt = 0;
        __syncthreads();

        unsigned int hi = (shift == 24) ? 0u : (0xFFFFFFFFu << (shift + 8));
        #pragma unroll
        for (int i = tid; i < QQ; i += 1024) {
            unsigned int u = keys[i];
            if ((u & hi) == prefix) atomicAdd(&ss->hist[(u >> shift) & 255u], 1u);
        }
        __syncthreads();

        if (tid < 256) {
            unsigned int cnt = ss->hist[tid];
            unsigned int v   = cnt;
            #pragma unroll
            for (int o = 1; o < 32; o <<= 1) {
                unsigned int y = __shfl_up_sync(0xFFFFFFFFu, v, o);
                if (lane >= o) v += y;
            }
            if (lane == 31) ss->wtot[wid] = v;
            __syncthreads();
            if (wid == 0 && lane < 8) {
                unsigned int t0 = ss->wtot[lane];
                unsigned int t  = t0;
                #pragma unroll
                for (int o = 1; o < 8; o <<= 1) {
                    unsigned int y = __shfl_up_sync(0x000000FFu, t, o);
                    if (lane >= o) t += y;
                }
                ss->wtot[lane] = t - t0;
            }
            __syncthreads();
            unsigned int inc = v + ss->wtot[wid];
            unsigned int exc = inc - cnt;
            if ((int)exc <= k && k < (int)inc) {
                ss->bc[0] = (unsigned int)tid;
                ss->bc[1] = (unsigned int)(k - (int)exc);
                ss->bc[2] = cnt;
            }
        } else {
            __syncthreads();
            __syncthreads();
        }
        __syncthreads();

        prefix |= (ss->bc[0] << shift);
        k = (int)ss->bc[1];
        unsigned int cnt = ss->bc[2];

        if (shift > 0 && cnt <= 64u) {
            unsigned int hi2 = 0xFFFFFFFFu << shift;
            #pragma unroll
            for (int i = tid; i < QQ; i += 1024) {
                unsigned int u = keys[i];
                if ((u & hi2) == prefix) {
                    unsigned int p = atomicAdd(&ss->ccnt, 1u);
                    ss->candu[p] = u;
                }
            }
            __syncthreads();
            if (tid < 32) {
                int n = (int)cnt;
                for (int i = tid; i < n; i += 32) {
                    unsigned int v = ss->candu[i];
                    int less = 0, eq = 0;
                    for (int j = 0; j < n; j++) {
                        unsigned int u = ss->candu[j];
                        less += (u < v);
                        eq   += (u == v);
                    }
                    if (less <= k && k < less + eq) ss->bc[2] = v;
                }
            }
            __syncthreads();
            return ss->bc[2];
        }
        __syncthreads();
    }
    return prefix;
}

// value accessor: mode 0 -> rs[i]; mode 1 -> |rs[i]-med|
__device__ __forceinline__ float sel_val(const float* rs, float med, int mode, int i) {
    return mode ? fabsf(rs[i] - med) : rs[i];
}

// exact k-th smallest (0-indexed) via linear binning; 1024 threads.
__device__ float lin_select(const float* rs, float med, int mode,
                            unsigned int* keys, SelShared* ss, int tid, int k) {
    int wid  = tid >> 5;
    int lane = tid & 31;

    // 1) min/max
    float mn = 3.4e38f, mx = -3.4e38f;
    #pragma unroll
    for (int i = tid; i < QQ; i += 1024) {
        float v = sel_val(rs, med, mode, i);
        mn = fminf(mn, v); mx = fmaxf(mx, v);
    }
    #pragma unroll
    for (int o = 16; o > 0; o >>= 1) {
        mn = fminf(mn, __shfl_xor_sync(0xFFFFFFFFu, mn, o));
        mx = fmaxf(mx, __shfl_xor_sync(0xFFFFFFFFu, mx, o));
    }
    if (lane == 0) { ss->smn[wid] = mn; ss->smx[wid] = mx; }
    __syncthreads();
    if (tid < 32) {
        mn = ss->smn[tid]; mx = ss->smx[tid];
        #pragma unroll
        for (int o = 16; o > 0; o >>= 1) {
            mn = fminf(mn, __shfl_xor_sync(0xFFFFFFFFu, mn, o));
            mx = fmaxf(mx, __shfl_xor_sync(0xFFFFFFFFu, mx, o));
        }
        if (tid == 0) { ss->smn[0] = mn; ss->smx[0] = mx; }
    }
    __syncthreads();
    float gmn = ss->smn[0], gmx = ss->smx[0];
    __syncthreads();
    if (!(gmx > gmn)) return gmn;     // all values identical
    float invw = 1024.0f / (gmx - gmn);

    // 2) linear histogram
    ss->hist[tid] = 0;
    if (tid == 0) ss->ccnt = 0;
    __syncthreads();
    #pragma unroll
    for (int i = tid; i < QQ; i += 1024) {
        float v = sel_val(rs, med, mode, i);
        int bin = min(1023, (int)((v - gmn) * invw));
        atomicAdd(&ss->hist[bin], 1u);
    }
    __syncthreads();

    // 3) scan 1024 bins (one per thread)
    unsigned int cnt = ss->hist[tid];
    unsigned int v = cnt;
    #pragma unroll
    for (int o = 1; o < 32; o <<= 1) {
        unsigned int y = __shfl_up_sync(0xFFFFFFFFu, v, o);
        if (lane >= o) v += y;
    }
    if (lane == 31) ss->wtot[wid] = v;
    __syncthreads();
    if (tid < 32) {
        unsigned int t0 = ss->wtot[tid];
        unsigned int t  = t0;
        #pragma unroll
        for (int o = 1; o < 32; o <<= 1) {
            unsigned int y = __shfl_up_sync(0xFFFFFFFFu, t, o);
            if (tid >= o) t += y;
        }
        ss->wtot[tid] = t - t0;
    }
    __syncthreads();
    unsigned int inc = v + ss->wtot[wid];
    unsigned int exc = inc - cnt;
    if ((int)exc <= k && k < (int)inc) {
        ss->bc[0] = (unsigned int)tid;
        ss->bc[1] = (unsigned int)(k - (int)exc);
        ss->bc[2] = cnt;
    }
    __syncthreads();
    int selbin      = (int)ss->bc[0];
    int kk          = (int)ss->bc[1];
    unsigned int c  = ss->bc[2];
    __syncthreads();

    if (c <= 128u) {
        // 4) gather + exact rank select
        #pragma unroll
        for (int i = tid; i < QQ; i += 1024) {
            float vv = sel_val(rs, med, mode, i);
            int bin = min(1023, (int)((vv - gmn) * invw));
            if (bin == selbin) {
                unsigned int p = atomicAdd(&ss->ccnt, 1u);
                ss->candf[p] = vv;
            }
        }
        __syncthreads();
        if (tid < (int)c) {
            float x = ss->candf[tid];
            int less = 0, eq = 0;
            for (int j = 0; j < (int)c; j++) {
                float u = ss->candf[j];
                less += (u < x);
                eq   += (u == x);
            }
            if (less <= kk && kk < less + eq) ss->result = x;
        }
        __syncthreads();
        float r = ss->result;
        __syncthreads();
        return r;
    }

    // fallback: exact radix select on monotone keys
    #pragma unroll
    for (int i = tid; i < QQ; i += 1024)
        keys[i] = fkey(sel_val(rs, med, mode, i));
    __syncthreads();
    return key_to_float(radix_select(keys, ss, tid, k));
}

__global__ __launch_bounds__(1024) void robust_kernel(float* __restrict__ out) {
    __shared__ float        rs[QQ];
    __shared__ unsigned int keys[QQ];
    __shared__ SelShared    ss;
    __shared__ float        red[32];

    int b   = blockIdx.x;
    int tid = threadIdx.x;

    #pragma unroll
    for (int i = tid; i < QQ; i += 1024)
        rs[i] = g_res[b * QQ + i];
    __syncthreads();

    float med = lin_select(rs, 0.0f, 0, keys, &ss, tid, (QQ - 1) / 2);
    __syncthreads();
    float mad = lin_select(rs, med, 1, keys, &ss, tid, (QQ - 1) / 2);

    float scale = (mad / 0.67449f) * 4.6851f;

    float sum = 0.0f;
    #pragma unroll
    for (int i = tid; i < QQ; i += 1024) {
        float r  = rs[i];
        float nr = r / scale;
        float t  = 1.0f - nr * nr;
        float w  = (nr >= 1.0f) ? 0.0f : t * t;
        sum += w * r * r;
    }

    #pragma unroll
    for (int o = 16; o > 0; o >>= 1)
        sum += __shfl_xor_sync(0xFFFFFFFFu, sum, o);
    if ((tid & 31) == 0) red[tid >> 5] = sum;
    __syncthreads();

    if (tid < 32) {
        float s = red[tid];
        #pragma unroll
        for (int o = 16; o > 0; o >>= 1)
            s += __shfl_xor_sync(0xFFFFFFFFu, s, o);
        if (tid == 0) {
            g_partial[b] = s;
            __threadfence();
            unsigned int prev = atomicAdd(&g_done, 1u);
            if (prev == BB - 1) {
                out[0] = 0.5f * (g_partial[0] + g_partial[1]);
                g_done = 0;  // reset for next graph replay
            }
        }
    }
}

extern "C" void kernel_launch(void* const* d_in, const int* in_sizes, int n_in,
                              void* d_out, int out_size) {
    const float* points = (const float*)d_in[0];  // (B,Q,3)
    const float* tris   = (const float*)d_in[1];  // (B,F,3,3)
    const float* occ    = (const float*)d_in[2];  // (B,Q)
    float* out = (float*)d_out;

    wn_kernel<<<(BB * QQ) / 4, 128>>>(points, tris, occ);
    robust_kernel<<<BB, 1024>>>(out);
}

// round 16
// speedup vs baseline: 1.0461x; 1.0461x over previous
#include <cuda_runtime.h>
#include <math.h>

#define BB 2
#define QQ 2048
#define FF 1538
#define CH 514          // faces per smem chunk (3 chunks cover 1538)

__device__ float g_res[BB * QQ];
__device__ float g_partial[BB];
__device__ unsigned int g_done = 0;

// ---------------------------------------------------------------------------
// fast helpers
// ---------------------------------------------------------------------------
__device__ __forceinline__ float sqrt_approx(float x) {
    float r; asm("sqrt.approx.f32 %0, %1;" : "=f"(r) : "f"(x)); return r;
}
__device__ __forceinline__ float rcp_approx(float x) {
    float r; asm("rcp.approx.f32 %0, %1;" : "=f"(r) : "f"(x)); return r;
}

// atan2 via quadrant folding + degree-11 odd minimax poly (|err| ~ 3e-6)
__device__ __forceinline__ float fast_atan2(float y, float x) {
    float ax = fabsf(x), ay = fabsf(y);
    float mx = fmaxf(ax, ay), mn = fminf(ax, ay);
    float t = mn * rcp_approx(mx);
    float s = t * t;
    float p =             -0.01172120f;
    p = fmaf(p, s,  0.05265332f);
    p = fmaf(p, s, -0.11643287f);
    p = fmaf(p, s,  0.19354346f);
    p = fmaf(p, s, -0.33262347f);
    p = fmaf(p, s,  0.99997726f);
    float r = p * t;
    if (ay > ax) r = 1.57079632679f - r;
    if (x < 0.0f) r = 3.14159265359f - r;
    return copysignf(r, y);
}

// one face (from smem float4s) against one query point -> solid-angle atan term
__device__ __forceinline__ float face_term(const float4 v0, const float4 v1,
                                           const float4 v2,
                                           float px, float py, float pz) {
    float ax = v0.x - px, ay = v0.y - py, az = v0.z - pz;
    float bx = v0.w - px, by = v1.x - py, bz = v1.y - pz;
    float cx = v1.z - px, cy = v1.w - py, cz = v2.x - pz;

    float na = sqrt_approx(fmaf(ax, ax, fmaf(ay, ay, az * az)));
    float nb = sqrt_approx(fmaf(bx, bx, fmaf(by, by, bz * bz)));
    float nc = sqrt_approx(fmaf(cx, cx, fmaf(cy, cy, cz * cz)));

    float crx = by * cz - bz * cy;
    float cry = bz * cx - bx * cz;
    float crz = bx * cy - by * cx;

    float num = fmaf(ax, crx, fmaf(ay, cry, az * crz));
    float d01 = fmaf(ax, bx, fmaf(ay, by, az * bz));
    float d12 = fmaf(bx, cx, fmaf(by, cy, bz * cz));
    float d02 = fmaf(ax, cx, fmaf(ay, cy, az * cz));

    float den = fmaf(na * nb, nc, fmaf(d01, nc, fmaf(d02, nb, d12 * na)));
    return fast_atan2(num, den);
}

// ---------------------------------------------------------------------------
// Kernel 1: winding numbers + residuals (R6 form + face-level unroll 2).
// TWO queries per warp (ILP=2) and TWO warps per query pair (face split).
// 128-thread blocks, 4 queries/block -> 1024 blocks.
// ---------------------------------------------------------------------------
__global__ __launch_bounds__(128) void wn_kernel(const float* __restrict__ points,
                                                 const float* __restrict__ tris,
                                                 const float* __restrict__ occ) {
    __shared__ float st[CH * 12];
    __shared__ float sacc[8];     // [warp*2 + whichQuery]

    int tid  = threadIdx.x;
    int warp = tid >> 5;          // 0..3
    int lane = tid & 31;
    int pair = warp >> 1;         // query pair 0/1 within block
    int half = warp & 1;          // face-stride half

    int qA = blockIdx.x * 4 + pair * 2;   // 1024 blocks * 4 queries = 4096
    int qB = qA + 1;
    int b  = qA >> 11;                    // batch (uniform per block)

    float pxA = points[qA * 3 + 0], pyA = points[qA * 3 + 1], pzA = points[qA * 3 + 2];
    float pxB = points[qB * 3 + 0], pyB = points[qB * 3 + 1], pzB = points[qB * 3 + 2];

    const float* tb = tris + (size_t)b * FF * 9;

    float accA = 0.0f, accB = 0.0f;
    for (int base = 0; base < FF; base += CH) {
        int nf = min(CH, FF - base);
        __syncthreads();
        // stage: one face per thread, strided (no integer division)
        for (int f = tid; f < nf; f += 128) {
            const float* src = tb + (size_t)(base + f) * 9;
            float* dst = &st[f * 12];
            #pragma unroll
            for (int c = 0; c < 9; c++) dst[c] = src[c];
        }
        __syncthreads();

        int f = half * 32 + lane;
        // unrolled-by-2: two faces in flight -> 4 independent chains/lane
        for (; f + 64 < nf; f += 128) {
            const float4* t4a = (const float4*)&st[f * 12];
            float4 u0 = t4a[0], u1 = t4a[1], u2 = t4a[2];
            const float4* t4b = (const float4*)&st[(f + 64) * 12];
            float4 w0 = t4b[0], w1 = t4b[1], w2 = t4b[2];

            accA += face_term(u0, u1, u2, pxA, pyA, pzA);
            accB += face_term(u0, u1, u2, pxB, pyB, pzB);
            accA += face_term(w0, w1, w2, pxA, pyA, pzA);
            accB += face_term(w0, w1, w2, pxB, pyB, pzB);
        }
        for (; f < nf; f += 64) {
            const float4* t4 = (const float4*)&st[f * 12];
            float4 v0 = t4[0], v1 = t4[1], v2 = t4[2];
            accA += face_term(v0, v1, v2, pxA, pyA, pzA);
            accB += face_term(v0, v1, v2, pxB, pyB, pzB);
        }
    }

    #pragma unroll
    for (int o = 16; o > 0; o >>= 1) {
        accA += __shfl_xor_sync(0xFFFFFFFFu, accA, o);
        accB += __shfl_xor_sync(0xFFFFFFFFu, accB, o);
    }

    if (lane == 0) {
        sacc[warp * 2 + 0] = accA;
        sacc[warp * 2 + 1] = accB;
    }
    __syncthreads();

    if (tid < 4) {  // tid = local query index 0..3
        int p    = tid >> 1;
        int qloc = tid & 1;
        float tot = sacc[(p * 2 + 0) * 2 + qloc] + sacc[(p * 2 + 1) * 2 + qloc];
        int q = blockIdx.x * 4 + tid;
        float wn = tot * 0.15915494309189535f;   // (2*atan2 sum)/(4*pi)
        g_res[q] = wn - occ[q];
    }
}

// ---------------------------------------------------------------------------
// Kernel 2: robust weighting (EXACT R6 version, proven ~9.5us floor).
// 1024 threads/batch; 8-bit radix-select + early small-select (<=64).
// ---------------------------------------------------------------------------
__device__ __forceinline__ unsigned int fkey(float f) {
    unsigned int u = __float_as_uint(f);
    return (u & 0x80000000u) ? ~u : (u | 0x80000000u);
}
__device__ __forceinline__ float key_to_float(unsigned int k) {
    unsigned int bits = (k & 0x80000000u) ? (k ^ 0x80000000u) : ~k;
    return __uint_as_float(bits);
}

struct SelShared {
    unsigned int hist[256];
    unsigned int wtot[8];
    unsigned int bc[3];      // bin, new k, bin count / result value
    unsigned int cand[64];
    unsigned int ccnt;
};

__device__ unsigned int radix_select(const unsigned int* keys, SelShared* ss,
                                     int tid, int k) {
    int wid  = tid >> 5;
    int lane = tid & 31;
    unsigned int prefix = 0;

    for (int shift = 24; shift >= 0; shift -= 8) {
        if (tid < 256) ss->hist[tid] = 0;
        if (tid == 0)  ss->ccnt = 0;
        __syncthreads();

        unsigned int hi = (shift == 24) ? 0u : (0xFFFFFFFFu << (shift + 8));
        #pragma unroll
        for (int i = tid; i < QQ; i += 1024) {
            unsigned int u = keys[i];
            if ((u & hi) == prefix) atomicAdd(&ss->hist[(u >> shift) & 255u], 1u);
        }
        __syncthreads();

        if (tid < 256) {
            unsigned int cnt = ss->hist[tid];
            unsigned int v   = cnt;
            #pragma unroll
            for (int o = 1; o < 32; o <<= 1) {
                unsigned int y = __shfl_up_sync(0xFFFFFFFFu, v, o);
                if (lane >= o) v += y;
            }
            if (lane == 31) ss->wtot[wid] = v;
            __syncthreads();

            if (wid == 0 && lane < 8) {
                unsigned int t0 = ss->wtot[lane];
                unsigned int t  = t0;
                #pragma unroll
                for (int o = 1; o < 8; o <<= 1) {
                    unsigned int y = __shfl_up_sync(0x000000FFu, t, o);
                    if (lane >= o) t += y;
                }
                ss->wtot[lane] = t - t0;
            }
            __syncthreads();

            unsigned int inc = v + ss->wtot[wid];
            unsigned int exc = inc - cnt;
            if ((int)exc <= k && k < (int)inc) {
                ss->bc[0] = (unsigned int)tid;
                ss->bc[1] = (unsigned int)(k - (int)exc);
                ss->bc[2] = cnt;
            }
        } else {
            __syncthreads();
            __syncthreads();
        }
        __syncthreads();

        prefix |= (ss->bc[0] << shift);
        k = (int)ss->bc[1];
        unsigned int cnt = ss->bc[2];

        if (shift > 0 && cnt <= 64u) {
            unsigned int hi2 = 0xFFFFFFFFu << shift;
            #pragma unroll
            for (int i = tid; i < QQ; i += 1024) {
                unsigned int u = keys[i];
                if ((u & hi2) == prefix) {
                    unsigned int p = atomicAdd(&ss->ccnt, 1u);
                    ss->cand[p] = u;
                }
            }
            __syncthreads();
            if (tid < 32) {
                int n = (int)cnt;
                for (int i = tid; i < n; i += 32) {
                    unsigned int v = ss->cand[i];
                    int less = 0, eq = 0;
                    for (int j = 0; j < n; j++) {
                        unsigned int u = ss->cand[j];
                        less += (u < v);
                        eq   += (u == v);
                    }
                    if (less <= k && k < less + eq) ss->bc[2] = v;
                }
            }
            __syncthreads();
            return ss->bc[2];
        }
        __syncthreads();
    }
    return prefix;
}

__global__ __launch_bounds__(1024) void robust_kernel(float* __restrict__ out) {
    __shared__ float        rs[QQ];
    __shared__ unsigned int keys[QQ];
    __shared__ SelShared    ss;
    __shared__ float        red[32];

    int b   = blockIdx.x;
    int tid = threadIdx.x;

    #pragma unroll
    for (int i = tid; i < QQ; i += 1024) {
        float v = g_res[b * QQ + i];
        rs[i]   = v;
        keys[i] = fkey(v);
    }
    __syncthreads();

    float med = key_to_float(radix_select(keys, &ss, tid, (QQ - 1) / 2));
    __syncthreads();

    #pragma unroll
    for (int i = tid; i < QQ; i += 1024)
        keys[i] = fkey(fabsf(rs[i] - med));
    __syncthreads();

    float mad = key_to_float(radix_select(keys, &ss, tid, (QQ - 1) / 2));

    float scale = (mad / 0.67449f) * 4.6851f;

    float sum = 0.0f;
    #pragma unroll
    for (int i = tid; i < QQ; i += 1024) {
        float r  = rs[i];
        float nr = r / scale;
        float t  = 1.0f - nr * nr;
        float w  = (nr >= 1.0f) ? 0.0f : t * t;
        sum += w * r * r;
    }

    #pragma unroll
    for (int o = 16; o > 0; o >>= 1)
        sum += __shfl_xor_sync(0xFFFFFFFFu, sum, o);
    if ((tid & 31) == 0) red[tid >> 5] = sum;
    __syncthreads();

    if (tid < 32) {
        float s = red[tid];
        #pragma unroll
        for (int o = 16; o > 0; o >>= 1)
            s += __shfl_xor_sync(0xFFFFFFFFu, s, o);
        if (tid == 0) {
            g_partial[b] = s;
            __threadfence();
            unsigned int prev = atomicAdd(&g_done, 1u);
            if (prev == BB - 1) {
                out[0] = 0.5f * (g_partial[0] + g_partial[1]);
                g_done = 0;  // reset for next graph replay
            }
        }
    }
}

extern "C" void kernel_launch(void* const* d_in, const int* in_sizes, int n_in,
                              void* d_out, int out_size) {
    const float* points = (const float*)d_in[0];  // (B,Q,3)
    const float* tris   = (const float*)d_in[1];  // (B,F,3,3)
    const float* occ    = (const float*)d_in[2];  // (B,Q)
    float* out = (float*)d_out;

    wn_kernel<<<(BB * QQ) / 4, 128>>>(points, tris, occ);
    robust_kernel<<<BB, 1024>>>(out);
}